// round 16
// baseline (speedup 1.0000x reference)
#include <cuda_runtime.h>
#include <cstdint>

#define D          256
#define NCODES     1024
#define ROWS_TOTAL 16384
#define BM         128
#define BN         256
#define NCHUNK     8         // 4 n-blocks x 2 k-chunks of 128
#define CAP        32
#define NT         512

#define ASTRIDE_B   160      // 128 data + 32 pad, conflict-free for 32B/row groups
#define ACHUNK_B    (BM * ASTRIDE_B)              // 20480
#define A_FULL      0                             // 2 k-chunks resident: 40960
#define B_OFF       40960
#define B_STAGE     (BN * ASTRIDE_B)              // 40960
#define NSTAGE      3
#define EHALF_OFF   (B_OFF + NSTAGE * B_STAGE)    // 163840
#define ESC_OFF     (EHALF_OFF + NCODES * 4)      // 167936
#define SX_OFF      (ESC_OFF + NCODES * 4)        // 172032
#define SM_OFF      (SX_OFF + BM * 4)             // 172544
#define SMAX_OFF    (SM_OFF + BM * 4)             // 173056
#define SCNT_OFF    (SMAX_OFF + BM * 4)           // 173568
#define SIDX_OFF    (SCNT_OFF + BM * 4)           // 174080
#define SLIST_OFF   (SIDX_OFF + BM * 4)           // 174592
#define SMEM_TOTAL  (SLIST_OFF + BM * CAP * 8)    // 207360

__device__ char   g_Ec[(size_t)NCODES * D];        // int8 codes, word-interleaved
__device__ float  g_e_half[NCODES];
__device__ float  g_es[NCODES];                    // per-code scale se
__device__ int    g_semax_bits;                    // atomicMax idempotent across replays
__device__ int    g_el1max_bits;

__device__ __forceinline__ constexpr int posw(int w) {   // word interleave in 32-byte group
    return 2 * (w & 3) + (w >> 2);
}
__device__ __forceinline__ unsigned fenc(float f) {
    unsigned u = __float_as_uint(f);
    return (u & 0x80000000u) ? ~u : (u | 0x80000000u);
}
__device__ __forceinline__ float fdec(unsigned u) {
    return __uint_as_float((u & 0x80000000u) ? (u ^ 0x80000000u) : ~u);
}
__device__ __forceinline__ unsigned pack4(float a, float b, float c, float d, float r) {
    int q0 = max(-127, min(127, __float2int_rn(a * r)));
    int q1 = max(-127, min(127, __float2int_rn(b * r)));
    int q2 = max(-127, min(127, __float2int_rn(c * r)));
    int q3 = max(-127, min(127, __float2int_rn(d * r)));
    return (unsigned)(q0 & 0xFF) | ((unsigned)(q1 & 0xFF) << 8)
         | ((unsigned)(q2 & 0xFF) << 16) | ((unsigned)(q3 & 0xFF) << 24);
}

// one warp per code row: scales, l1, e_half, quantize+interleave
__global__ void prep_e(const float* __restrict__ E) {
    const int lane = threadIdx.x & 31;
    const int row  = blockIdx.x * 8 + (threadIdx.x >> 5);
    const float4* er = reinterpret_cast<const float4*>(E + (size_t)row * D);
    float4 v0 = er[2 * lane], v1 = er[2 * lane + 1];    // k = 8*lane .. +7
    const float f[8] = { v0.x, v0.y, v0.z, v0.w, v1.x, v1.y, v1.z, v1.w };
    float mx = 0.f, l1 = 0.f, sq = 0.f;
#pragma unroll
    for (int j = 0; j < 8; j++) { float a = fabsf(f[j]); mx = fmaxf(mx, a); l1 += a; sq += f[j] * f[j]; }
#pragma unroll
    for (int off = 16; off > 0; off >>= 1) {
        mx = fmaxf(mx, __shfl_xor_sync(0xffffffffu, mx, off));
        l1 += __shfl_xor_sync(0xffffffffu, l1, off);
        sq += __shfl_xor_sync(0xffffffffu, sq, off);
    }
    const float se  = fmaxf(mx, 1e-30f) / 127.f;
    const float rse = 127.f / fmaxf(mx, 1e-30f);
    if (lane == 0) {
        g_es[row] = se;
        g_e_half[row] = 0.5f * sq;
        atomicMax(&g_semax_bits, __float_as_int(se));
        atomicMax(&g_el1max_bits, __float_as_int(l1));
    }
    unsigned w0 = pack4(f[0], f[1], f[2], f[3], rse);
    unsigned w1 = pack4(f[4], f[5], f[6], f[7], rse);
    const int g32 = lane >> 2;                    // 32-elem group
    const int wA = (2 * lane) & 7;
    char* base = g_Ec + (size_t)row * D + g32 * 32;
    *reinterpret_cast<unsigned*>(base + 4 * posw(wA))     = w0;
    *reinterpret_cast<unsigned*>(base + 4 * posw(wA + 1)) = w1;
}

static __device__ __forceinline__ uint32_t smem_u32(const void* p) {
    uint32_t a;
    asm("{ .reg .u64 t; cvta.to.shared.u64 t, %1; cvt.u32.u64 %0, t; }" : "=r"(a) : "l"(p));
    return a;
}
#define CP16(dst, src) asm volatile("cp.async.cg.shared.global [%0], [%1], 16;" :: "r"(dst), "l"(src) : "memory")
#define LDS64(r0, r1, a) asm volatile("ld.shared.v2.b32 {%0,%1}, [%2];" : "=r"(r0), "=r"(r1) : "r"(a))
#define MMA_S8(c, a, b) \
    asm volatile("mma.sync.aligned.m16n8k32.row.col.s32.s8.s8.s32 " \
                 "{%0,%1,%2,%3}, {%4,%5,%6,%7}, {%8,%9}, {%0,%1,%2,%3};" \
                 : "+r"((c)[0]), "+r"((c)[1]), "+r"((c)[2]), "+r"((c)[3]) \
                 : "r"((a)[0]), "r"((a)[1]), "r"((a)[2]), "r"((a)[3]), "r"((b)[0]), "r"((b)[1]))

// double-float helpers (fp32 pipe; FP64 is fused-off on B300)
__device__ __forceinline__ void df_renorm(float& h, float& l) {
    float s = h + l; l = l - (s - h); h = s;
}
__device__ __forceinline__ void df_add(float& ah, float& al, float bh, float bl) {
    float s = ah + bh;
    float v = s - ah;
    float e = (ah - (s - v)) + (bh - v);
    float l = e + al + bl;
    ah = s; al = l;
    df_renorm(ah, al);
}
__device__ __forceinline__ void cscore(const float* __restrict__ E, int idx, int lane,
                                       const float xv[8], float& h, float& l) {
    const float4* E4r = reinterpret_cast<const float4*>(E + (size_t)idx * D);
    float4 e0 = E4r[lane], e1 = E4r[lane + 32];
    const float ev[8] = { e0.x, e0.y, e0.z, e0.w, e1.x, e1.y, e1.z, e1.w };
    float s = 0.f, comp = 0.f;
#pragma unroll
    for (int j = 0; j < 8; j++) {
        float p    = fmaf(-0.5f, ev[j], xv[j]);
        float prod = ev[j] * p;
        float perr = fmaf(ev[j], p, -prod);
        float tsum = s + prod;
        float v    = tsum - s;
        float serr = (s - (tsum - v)) + (prod - v);
        s = tsum; comp += serr + perr;
    }
    h = s; l = comp;
    df_renorm(h, l);
#pragma unroll
    for (int off = 16; off > 0; off >>= 1) {
        float oh = __shfl_xor_sync(0xffffffffu, h, off);
        float ol = __shfl_xor_sync(0xffffffffu, l, off);
        df_add(h, l, oh, ol);
    }
}
__device__ __noinline__ int full_scan(const float* __restrict__ X,
                                      const float* __restrict__ E,
                                      int grow, int lane) {
    const float4* X4 = reinterpret_cast<const float4*>(X + (size_t)grow * D);
    float4 x0 = X4[lane], x1 = X4[lane + 32];
    const float xv[8] = { x0.x, x0.y, x0.z, x0.w, x1.x, x1.y, x1.z, x1.w };
    float bh = -3.4e38f, bl = 0.f;
    int besti = NCODES;
    for (int idx = 0; idx < NCODES; idx++) {
        float h, l;
        cscore(E, idx, lane, xv, h, l);
        bool gt = (h > bh) || (h == bh && l > bl);
        bool eq = (h == bh) && (l == bl);
        if (gt || (eq && idx < besti)) { bh = h; bl = l; besti = idx; }
    }
    return besti;
}

__global__ __launch_bounds__(NT, 1)
void vq_mma(const float* __restrict__ X, const float* __restrict__ E,
            float* __restrict__ out) {
    extern __shared__ char smem[];
    const uint32_t sb = smem_u32(smem);
    float*    ehs   = (float*)(smem + EHALF_OFF);
    float*    ses   = (float*)(smem + ESC_OFF);
    float*    sXs   = (float*)(smem + SX_OFF);
    float*    sM    = (float*)(smem + SM_OFF);
    unsigned* sMax  = (unsigned*)(smem + SMAX_OFF);
    int*      sCnt  = (int*)(smem + SCNT_OFF);
    int*      sIdx  = (int*)(smem + SIDX_OFF);
    int2*     sList = (int2*)(smem + SLIST_OFF);

    const int tid  = threadIdx.x;
    const int lane = tid & 31, wid = tid >> 5;
    const int wm = wid & 3, wn = wid >> 2;              // 4(M) x 4(N)
    const int g = lane >> 2, t = lane & 3;
    const int row0 = blockIdx.x * BM;
    const float seMax  = __int_as_float(g_semax_bits);
    const float el1Max = __int_as_float(g_el1max_bits);

    // B cp.async: 256 rows x 8 units(16B) = 2048 units / 512 thr = 4 units
    const int urow = tid >> 3, uj = tid & 7;            // urow 0..63
    const char* bSrcB = g_Ec + (size_t)urow * D + uj * 16;
    const uint32_t bDst0 = sb + B_OFF + urow * ASTRIDE_B + uj * 16;
    const uint32_t aLds0 = sb + (uint32_t)(A_FULL + (wm * 32 + g) * ASTRIDE_B + t * 8);
    const uint32_t bLds0 = sb + (uint32_t)(B_OFF + (wn * 64 + g) * ASTRIDE_B + t * 8);

    // chunk c: nb = c>>1, kc = c&1; stage = c % 3
#define ISSUE_B(c) do {                                                          \
        const uint32_t _st = (uint32_t)((c) % NSTAGE) * B_STAGE;                 \
        const int _boff = ((c) >> 1) * 65536 + ((c) & 1) * 128;                  \
        _Pragma("unroll")                                                        \
        for (int i = 0; i < 4; i++) CP16(_st + bDst0 + i * (64 * ASTRIDE_B),     \
                                         bSrcB + _boff + i * 16384);             \
        asm volatile("cp.async.commit_group;" ::: "memory");                     \
    } while (0)

    ISSUE_B(0);
    ISSUE_B(1);

    // ---- fused prep_x: two-pass quantize X rows into resident int8 A-tile ----
    {
        const int crow = tid >> 2, cq = tid & 3;        // 4 threads per row, 64 elems each
        const float4* xr = reinterpret_cast<const float4*>(X + (size_t)(row0 + crow) * D) + cq * 16;
        float mx = 0.f, l1 = 0.f;
#pragma unroll
        for (int i = 0; i < 16; i++) {
            float4 v = xr[i];
            mx = fmaxf(mx, fmaxf(fmaxf(fabsf(v.x), fabsf(v.y)), fmaxf(fabsf(v.z), fabsf(v.w))));
            l1 += fabsf(v.x) + fabsf(v.y) + fabsf(v.z) + fabsf(v.w);
        }
        mx = fmaxf(mx, __shfl_xor_sync(0xffffffffu, mx, 1));
        mx = fmaxf(mx, __shfl_xor_sync(0xffffffffu, mx, 2));
        l1 += __shfl_xor_sync(0xffffffffu, l1, 1);
        l1 += __shfl_xor_sync(0xffffffffu, l1, 2);
        const float sx  = fmaxf(mx, 1e-30f) / 127.f;
        const float rsx = 127.f / fmaxf(mx, 1e-30f);
        if (cq == 0) {
            sXs[crow] = sx;
            // certified margin: 2x screening bound + fp slack
            sM[crow] = seMax * (l1 + 128.f * sx) + sx * (el1Max + 128.f * seMax)
                     + 128.f * sx * seMax + 0.1f;
        }
#pragma unroll
        for (int h = 0; h < 2; h++) {                   // two 32-elem groups
            unsigned ow[8];
#pragma unroll
            for (int w = 0; w < 8; w++) {
                float4 v = xr[h * 8 + w];
                ow[posw(w)] = pack4(v.x, v.y, v.z, v.w, rsx);
            }
            const int gg = 2 * cq + h;                  // global group 0..7
            char* dst = smem + A_FULL + (gg >> 2) * ACHUNK_B + crow * ASTRIDE_B + (gg & 3) * 32;
            reinterpret_cast<uint4*>(dst)[0] = make_uint4(ow[0], ow[1], ow[2], ow[3]);
            reinterpret_cast<uint4*>(dst)[1] = make_uint4(ow[4], ow[5], ow[6], ow[7]);
        }
    }

    for (int i = tid; i < NCODES; i += NT) { ehs[i] = g_e_half[i]; ses[i] = g_es[i]; }
    if (tid < BM) { sMax[tid] = 0u; sCnt[tid] = 0; }

    int acc[2][8][4];
#pragma unroll
    for (int mi = 0; mi < 2; mi++)
#pragma unroll
        for (int nj = 0; nj < 8; nj++)
#pragma unroll
            for (int q = 0; q < 4; q++) acc[mi][nj][q] = 0;

#pragma unroll 1
    for (int c = 0; c < NCHUNK; c++) {
        if (c < NCHUNK - 1) asm volatile("cp.async.wait_group 1;" ::: "memory");
        else                asm volatile("cp.async.wait_group 0;" ::: "memory");
        __syncthreads();     // stage c visible; all warps done with stage c-1; covers prep_x

        const uint32_t stB = (uint32_t)(c % NSTAGE) * B_STAGE;
        const uint32_t stA = (uint32_t)(c & 1) * ACHUNK_B;
#pragma unroll
        for (int s = 0; s < 4; s++) {                   // 4 k-steps of 32
            uint32_t a[2][4];
#pragma unroll
            for (int mi = 0; mi < 2; mi++) {
                uint32_t ad = stA + aLds0 + (uint32_t)(mi * 16 * ASTRIDE_B + s * 32);
                LDS64(a[mi][0], a[mi][2], ad);
                LDS64(a[mi][1], a[mi][3], ad + 8 * ASTRIDE_B);
            }
            uint32_t b[8][2];
#pragma unroll
            for (int nj = 0; nj < 8; nj++) {
                uint32_t bd = stB + bLds0 + (uint32_t)(nj * 8 * ASTRIDE_B + s * 32);
                LDS64(b[nj][0], b[nj][1], bd);
            }
#pragma unroll
            for (int mi = 0; mi < 2; mi++)
#pragma unroll
                for (int nj = 0; nj < 8; nj++)
                    MMA_S8(acc[mi][nj], a[mi], b[nj]);
        }

        if ((c & 1) == 1) {                      // end of n-block: dequant + phases
            const int n0 = (c >> 1) * BN;
#pragma unroll
            for (int mi = 0; mi < 2; mi++)
#pragma unroll
                for (int qh = 0; qh < 2; qh++) {
                    const int r = wm * 32 + mi * 16 + g + 8 * qh;
                    const float sxr = sXs[r];
                    float m = -3.4e38f;
#pragma unroll
                    for (int nj = 0; nj < 8; nj++) {
                        const int n = n0 + wn * 64 + nj * 8 + 2 * t;
                        float s0 = fmaf(__int2float_rn(acc[mi][nj][2 * qh]),
                                        sxr * ses[n], -ehs[n]);
                        float s1 = fmaf(__int2float_rn(acc[mi][nj][2 * qh + 1]),
                                        sxr * ses[n + 1], -ehs[n + 1]);
                        acc[mi][nj][2 * qh]     = __float_as_int(s0);   // store score in place
                        acc[mi][nj][2 * qh + 1] = __float_as_int(s1);
                        m = fmaxf(m, fmaxf(s0, s1));
                    }
                    m = fmaxf(m, __shfl_xor_sync(0xffffffffu, m, 1));
                    m = fmaxf(m, __shfl_xor_sync(0xffffffffu, m, 2));
                    if (t == 0) atomicMax(&sMax[r], fenc(m));
                }
#pragma unroll
            for (int mi = 0; mi < 2; mi++)
#pragma unroll
                for (int qh = 0; qh < 2; qh++) {
                    const int r = wm * 32 + mi * 16 + g + 8 * qh;
                    const float thr = fdec(sMax[r]) - sM[r];
#pragma unroll
                    for (int nj = 0; nj < 8; nj++) {
                        const int n = n0 + wn * 64 + nj * 8 + 2 * t;
#pragma unroll
                        for (int q = 0; q < 2; q++) {
                            float sc = __int_as_float(acc[mi][nj][2 * qh + q]);
                            if (sc >= thr) {
                                int p = atomicAdd(&sCnt[r], 1);
                                if (p < CAP)
                                    sList[r * CAP + p] = make_int2(__float_as_int(sc), n + q);
                            }
                        }
                    }
                }
#pragma unroll
            for (int mi = 0; mi < 2; mi++)
#pragma unroll
                for (int nj = 0; nj < 8; nj++)
#pragma unroll
                    for (int q = 0; q < 4; q++) acc[mi][nj][q] = 0;
        }
        if (c + 2 < NCHUNK) ISSUE_B(c + 2);
    }
    __syncthreads();                              // lists complete

    // ---- fused rescue: one warp per 8 rows ----
    for (int r = wid * 8; r < wid * 8 + 8; r++) {
        const int cnt = sCnt[r];
        int best = 0;
        if (cnt <= CAP) {
            float sc = -3.4e38f; int id = 0;
            if (lane < cnt) { int2 e = sList[r * CAP + lane]; sc = __int_as_float(e.x); id = e.y; }
            float msc = sc;
#pragma unroll
            for (int off = 16; off > 0; off >>= 1)
                msc = fmaxf(msc, __shfl_xor_sync(0xffffffffu, msc, off));
            const float thr = msc - sM[r];
            unsigned surv = __ballot_sync(0xffffffffu, lane < cnt && sc >= thr);
            if (__popc(surv) == 1) {
                best = __shfl_sync(0xffffffffu, id, __ffs(surv) - 1);
            } else {
                const float4* X4 = reinterpret_cast<const float4*>(X + (size_t)(row0 + r) * D);
                float4 x0 = X4[lane], x1 = X4[lane + 32];
                const float xv[8] = { x0.x, x0.y, x0.z, x0.w, x1.x, x1.y, x1.z, x1.w };
                float bh = -3.4e38f, bl = 0.f;
                int besti = NCODES;
                while (surv) {
                    int b = __ffs(surv) - 1; surv &= surv - 1;
                    int idx = __shfl_sync(0xffffffffu, id, b);
                    float h, l;
                    cscore(E, idx, lane, xv, h, l);
                    bool gt = (h > bh) || (h == bh && l > bl);
                    bool eq = (h == bh) && (l == bl);
                    if (gt || (eq && idx < besti)) { bh = h; bl = l; besti = idx; }
                }
                best = besti;
            }
        } else {
            best = full_scan(X, E, row0 + r, lane);   // cold, noinline
        }
        if (lane == 0) sIdx[r] = best;
    }
    __syncthreads();

    // ---- gather: out[row] = E[best] (coalesced float4) ----
    const float4* E4 = reinterpret_cast<const float4*>(E);
    float4*       O4 = reinterpret_cast<float4*>(out);
    const int col = tid & 63;
#pragma unroll
    for (int r = tid >> 6; r < BM; r += 8) {
        int idx = sIdx[r];
        O4[(size_t)(row0 + r) * (D / 4) + col] = E4[(size_t)idx * (D / 4) + col];
    }
#undef ISSUE_B
}

extern "C" void kernel_launch(void* const* d_in, const int* in_sizes, int n_in,
                              void* d_out, int out_size) {
    const float* x = (const float*)d_in[0];     // [16,1024,256] f32
    const float* E = (const float*)d_in[1];     // [1024,256]    f32
    float* out = (float*)d_out;

    prep_e<<<NCODES / 8, 256>>>(E);

    cudaFuncSetAttribute(vq_mma, cudaFuncAttributeMaxDynamicSharedMemorySize, SMEM_TOTAL);
    vq_mma<<<ROWS_TOTAL / BM, NT, SMEM_TOTAL>>>(x, E, out);
}

// round 17
// speedup vs baseline: 17.9992x; 17.9992x over previous
#include <cuda_runtime.h>
#include <cstdint>

#define D          256
#define NCODES     1024
#define ROWS_TOTAL 16384
#define BM         128
#define BN         256
#define NCHUNK     8         // 4 n-blocks x 2 k-chunks of 128
#define CAP        32
#define NT         512

#define ASTRIDE_B   160
#define ACHUNK_B    (BM * ASTRIDE_B)              // 20480
#define A_FULL      0                             // 2 k-chunks resident: 40960
#define B_OFF       40960
#define B_STAGE     (BN * ASTRIDE_B)              // 40960
#define NSTAGE      3
#define EHALF_OFF   (B_OFF + NSTAGE * B_STAGE)    // 163840
#define ESC_OFF     (EHALF_OFF + NCODES * 4)      // 167936
#define SX_OFF      (ESC_OFF + NCODES * 4)        // 172032
#define SM_OFF      (SX_OFF + BM * 4)             // 172544
#define SMAX_OFF    (SM_OFF + BM * 4)             // 173056
#define SCNT_OFF    (SMAX_OFF + BM * 4)           // 173568
#define SIDX_OFF    (SCNT_OFF + BM * 4)           // 174080
#define SLIST_OFF   (SIDX_OFF + BM * 4)           // 174592
#define SMEM_TOTAL  (SLIST_OFF + BM * CAP * 8)    // 207360

__device__ char   g_Ec[(size_t)NCODES * D];        // int8 codes, word-interleaved
__device__ float  g_e_half[NCODES];
__device__ float  g_es[NCODES];                    // per-code scale se
__device__ int    g_ee2max_bits;                   // max over codes of ||e - e_q||^2
__device__ int    g_eq2max_bits;                   // max over codes of ||e_q||^2

__device__ __forceinline__ constexpr int posw(int w) {   // word interleave in 32-byte group
    return 2 * (w & 3) + (w >> 2);
}
__device__ __forceinline__ unsigned fenc(float f) {
    unsigned u = __float_as_uint(f);
    return (u & 0x80000000u) ? ~u : (u | 0x80000000u);
}
__device__ __forceinline__ float fdec(unsigned u) {
    return __uint_as_float((u & 0x80000000u) ? (u ^ 0x80000000u) : ~u);
}

// one warp per code row: quantize, exact residual norms, e_half
__global__ void prep_e(const float* __restrict__ E) {
    const int lane = threadIdx.x & 31;
    const int row  = blockIdx.x * 8 + (threadIdx.x >> 5);
    const float4* er = reinterpret_cast<const float4*>(E + (size_t)row * D);
    float4 v0 = er[2 * lane], v1 = er[2 * lane + 1];    // k = 8*lane .. +7
    const float f[8] = { v0.x, v0.y, v0.z, v0.w, v1.x, v1.y, v1.z, v1.w };
    float mx = 0.f, sq = 0.f;
#pragma unroll
    for (int j = 0; j < 8; j++) { mx = fmaxf(mx, fabsf(f[j])); sq += f[j] * f[j]; }
#pragma unroll
    for (int off = 16; off > 0; off >>= 1) {
        mx = fmaxf(mx, __shfl_xor_sync(0xffffffffu, mx, off));
        sq += __shfl_xor_sync(0xffffffffu, sq, off);
    }
    const float se  = fmaxf(mx, 1e-30f) / 127.f;
    const float rse = 127.f / fmaxf(mx, 1e-30f);

    int qi[8];
    float eq2 = 0.f, ee2 = 0.f;
#pragma unroll
    for (int j = 0; j < 8; j++) {
        qi[j] = max(-127, min(127, __float2int_rn(f[j] * rse)));
        float eqv = (float)qi[j] * se;
        float rsd = f[j] - eqv;
        eq2 += eqv * eqv;
        ee2 += rsd * rsd;
    }
#pragma unroll
    for (int off = 16; off > 0; off >>= 1) {
        eq2 += __shfl_xor_sync(0xffffffffu, eq2, off);
        ee2 += __shfl_xor_sync(0xffffffffu, ee2, off);
    }
    if (lane == 0) {
        g_es[row] = se;
        g_e_half[row] = 0.5f * sq;
        atomicMax(&g_eq2max_bits, __float_as_int(eq2));   // nonneg: bit-monotone
        atomicMax(&g_ee2max_bits, __float_as_int(ee2));
    }
    unsigned w0 = (unsigned)(qi[0] & 0xFF) | ((unsigned)(qi[1] & 0xFF) << 8)
                | ((unsigned)(qi[2] & 0xFF) << 16) | ((unsigned)(qi[3] & 0xFF) << 24);
    unsigned w1 = (unsigned)(qi[4] & 0xFF) | ((unsigned)(qi[5] & 0xFF) << 8)
                | ((unsigned)(qi[6] & 0xFF) << 16) | ((unsigned)(qi[7] & 0xFF) << 24);
    const int g32 = lane >> 2;
    const int wA = (2 * lane) & 7;
    char* base = g_Ec + (size_t)row * D + g32 * 32;
    *reinterpret_cast<unsigned*>(base + 4 * posw(wA))     = w0;
    *reinterpret_cast<unsigned*>(base + 4 * posw(wA + 1)) = w1;
}

static __device__ __forceinline__ uint32_t smem_u32(const void* p) {
    uint32_t a;
    asm("{ .reg .u64 t; cvta.to.shared.u64 t, %1; cvt.u32.u64 %0, t; }" : "=r"(a) : "l"(p));
    return a;
}
#define CP16(dst, src) asm volatile("cp.async.cg.shared.global [%0], [%1], 16;" :: "r"(dst), "l"(src) : "memory")
#define LDS64(r0, r1, a) asm volatile("ld.shared.v2.b32 {%0,%1}, [%2];" : "=r"(r0), "=r"(r1) : "r"(a))
#define MMA_S8(c, a, b) \
    asm volatile("mma.sync.aligned.m16n8k32.row.col.s32.s8.s8.s32 " \
                 "{%0,%1,%2,%3}, {%4,%5,%6,%7}, {%8,%9}, {%0,%1,%2,%3};" \
                 : "+r"((c)[0]), "+r"((c)[1]), "+r"((c)[2]), "+r"((c)[3]) \
                 : "r"((a)[0]), "r"((a)[1]), "r"((a)[2]), "r"((a)[3]), "r"((b)[0]), "r"((b)[1]))

// double-float helpers (fp32 pipe; FP64 is fused-off on B300)
__device__ __forceinline__ void df_renorm(float& h, float& l) {
    float s = h + l; l = l - (s - h); h = s;
}
__device__ __forceinline__ void df_add(float& ah, float& al, float bh, float bl) {
    float s = ah + bh;
    float v = s - ah;
    float e = (ah - (s - v)) + (bh - v);
    float l = e + al + bl;
    ah = s; al = l;
    df_renorm(ah, al);
}
__device__ __forceinline__ void cscore(const float* __restrict__ E, int idx, int lane,
                                       const float xv[8], float& h, float& l) {
    const float4* E4r = reinterpret_cast<const float4*>(E + (size_t)idx * D);
    float4 e0 = E4r[lane], e1 = E4r[lane + 32];
    const float ev[8] = { e0.x, e0.y, e0.z, e0.w, e1.x, e1.y, e1.z, e1.w };
    float s = 0.f, comp = 0.f;
#pragma unroll
    for (int j = 0; j < 8; j++) {
        float p    = fmaf(-0.5f, ev[j], xv[j]);
        float prod = ev[j] * p;
        float perr = fmaf(ev[j], p, -prod);
        float tsum = s + prod;
        float v    = tsum - s;
        float serr = (s - (tsum - v)) + (prod - v);
        s = tsum; comp += serr + perr;
    }
    h = s; l = comp;
    df_renorm(h, l);
#pragma unroll
    for (int off = 16; off > 0; off >>= 1) {
        float oh = __shfl_xor_sync(0xffffffffu, h, off);
        float ol = __shfl_xor_sync(0xffffffffu, l, off);
        df_add(h, l, oh, ol);
    }
}
__device__ __noinline__ int full_scan(const float* __restrict__ X,
                                      const float* __restrict__ E,
                                      int grow, int lane) {
    const float4* X4 = reinterpret_cast<const float4*>(X + (size_t)grow * D);
    float4 x0 = X4[lane], x1 = X4[lane + 32];
    const float xv[8] = { x0.x, x0.y, x0.z, x0.w, x1.x, x1.y, x1.z, x1.w };
    float bh = -3.4e38f, bl = 0.f;
    int besti = NCODES;
    for (int idx = 0; idx < NCODES; idx++) {
        float h, l;
        cscore(E, idx, lane, xv, h, l);
        bool gt = (h > bh) || (h == bh && l > bl);
        bool eq = (h == bh) && (l == bl);
        if (gt || (eq && idx < besti)) { bh = h; bl = l; besti = idx; }
    }
    return besti;
}

__global__ __launch_bounds__(NT, 1)
void vq_mma(const float* __restrict__ X, const float* __restrict__ E,
            float* __restrict__ out) {
    extern __shared__ char smem[];
    const uint32_t sb = smem_u32(smem);
    float*    ehs   = (float*)(smem + EHALF_OFF);
    float*    ses   = (float*)(smem + ESC_OFF);
    float*    sXs   = (float*)(smem + SX_OFF);
    float*    sM    = (float*)(smem + SM_OFF);
    unsigned* sMax  = (unsigned*)(smem + SMAX_OFF);
    int*      sCnt  = (int*)(smem + SCNT_OFF);
    int*      sIdx  = (int*)(smem + SIDX_OFF);
    int2*     sList = (int2*)(smem + SLIST_OFF);

    const int tid  = threadIdx.x;
    const int lane = tid & 31, wid = tid >> 5;
    const int wm = wid & 3, wn = wid >> 2;              // 4(M) x 4(N)
    const int g = lane >> 2, t = lane & 3;
    const int row0 = blockIdx.x * BM;
    const float Ee = sqrtf(__int_as_float(g_ee2max_bits));   // max ||e - e_q||
    const float Eq = sqrtf(__int_as_float(g_eq2max_bits));   // max ||e_q||

    const int urow = tid >> 3, uj = tid & 7;
    const char* bSrcB = g_Ec + (size_t)urow * D + uj * 16;
    const uint32_t bDst0 = sb + B_OFF + urow * ASTRIDE_B + uj * 16;
    const uint32_t aLds0 = sb + (uint32_t)(A_FULL + (wm * 32 + g) * ASTRIDE_B + t * 8);
    const uint32_t bLds0 = sb + (uint32_t)(B_OFF + (wn * 64 + g) * ASTRIDE_B + t * 8);

#define ISSUE_B(c) do {                                                          \
        const uint32_t _st = (uint32_t)((c) % NSTAGE) * B_STAGE;                 \
        const int _boff = ((c) >> 1) * 65536 + ((c) & 1) * 128;                  \
        _Pragma("unroll")                                                        \
        for (int i = 0; i < 4; i++) CP16(_st + bDst0 + i * (64 * ASTRIDE_B),     \
                                         bSrcB + _boff + i * 16384);             \
        asm volatile("cp.async.commit_group;" ::: "memory");                     \
    } while (0)

    ISSUE_B(0);
    ISSUE_B(1);

    // ---- fused prep_x: quantize X into resident int8 A-tile; exact residual norms ----
    {
        const int crow = tid >> 2, cq = tid & 3;        // 4 threads per row, 64 elems each
        const float4* xr = reinterpret_cast<const float4*>(X + (size_t)(row0 + crow) * D) + cq * 16;
        float mx = 0.f, xsq = 0.f;
#pragma unroll
        for (int i = 0; i < 16; i++) {
            float4 v = xr[i];
            mx = fmaxf(mx, fmaxf(fmaxf(fabsf(v.x), fabsf(v.y)), fmaxf(fabsf(v.z), fabsf(v.w))));
            xsq += v.x * v.x + v.y * v.y + v.z * v.z + v.w * v.w;
        }
        mx = fmaxf(mx, __shfl_xor_sync(0xffffffffu, mx, 1));
        mx = fmaxf(mx, __shfl_xor_sync(0xffffffffu, mx, 2));
        xsq += __shfl_xor_sync(0xffffffffu, xsq, 1);
        xsq += __shfl_xor_sync(0xffffffffu, xsq, 2);
        const float sx  = fmaxf(mx, 1e-30f) / 127.f;
        const float rsx = 127.f / fmaxf(mx, 1e-30f);

        float ex2 = 0.f;
#pragma unroll
        for (int h = 0; h < 2; h++) {                   // two 32-elem groups
            unsigned ow[8];
#pragma unroll
            for (int w = 0; w < 8; w++) {
                float4 v = xr[h * 8 + w];
                int q0 = max(-127, min(127, __float2int_rn(v.x * rsx)));
                int q1 = max(-127, min(127, __float2int_rn(v.y * rsx)));
                int q2 = max(-127, min(127, __float2int_rn(v.z * rsx)));
                int q3 = max(-127, min(127, __float2int_rn(v.w * rsx)));
                float r0 = fmaf(-(float)q0, sx, v.x);
                float r1 = fmaf(-(float)q1, sx, v.y);
                float r2 = fmaf(-(float)q2, sx, v.z);
                float r3 = fmaf(-(float)q3, sx, v.w);
                ex2 += r0 * r0 + r1 * r1 + r2 * r2 + r3 * r3;
                ow[posw(w)] = (unsigned)(q0 & 0xFF) | ((unsigned)(q1 & 0xFF) << 8)
                            | ((unsigned)(q2 & 0xFF) << 16) | ((unsigned)(q3 & 0xFF) << 24);
            }
            const int gg = 2 * cq + h;
            char* dst = smem + A_FULL + (gg >> 2) * ACHUNK_B + crow * ASTRIDE_B + (gg & 3) * 32;
            reinterpret_cast<uint4*>(dst)[0] = make_uint4(ow[0], ow[1], ow[2], ow[3]);
            reinterpret_cast<uint4*>(dst)[1] = make_uint4(ow[4], ow[5], ow[6], ow[7]);
        }
        ex2 += __shfl_xor_sync(0xffffffffu, ex2, 1);
        ex2 += __shfl_xor_sync(0xffffffffu, ex2, 2);
        if (cq == 0) {
            sXs[crow] = sx;
            // certified Cauchy-Schwarz margin: ||x||*maxEe + maxEq*||ex|| + fp slack
            sM[crow] = sqrtf(xsq) * Ee + Eq * sqrtf(ex2) + 0.05f;
        }
    }

    for (int i = tid; i < NCODES; i += NT) { ehs[i] = g_e_half[i]; ses[i] = g_es[i]; }
    if (tid < BM) { sMax[tid] = 0u; sCnt[tid] = 0; }

    int acc[2][8][4];
#pragma unroll
    for (int mi = 0; mi < 2; mi++)
#pragma unroll
        for (int nj = 0; nj < 8; nj++)
#pragma unroll
            for (int q = 0; q < 4; q++) acc[mi][nj][q] = 0;

#pragma unroll 1
    for (int c = 0; c < NCHUNK; c++) {
        if (c < NCHUNK - 1) asm volatile("cp.async.wait_group 1;" ::: "memory");
        else                asm volatile("cp.async.wait_group 0;" ::: "memory");
        __syncthreads();

        const uint32_t stB = (uint32_t)(c % NSTAGE) * B_STAGE;
        const uint32_t stA = (uint32_t)(c & 1) * ACHUNK_B;
#pragma unroll
        for (int s = 0; s < 4; s++) {                   // 4 k-steps of 32
            uint32_t a[2][4];
#pragma unroll
            for (int mi = 0; mi < 2; mi++) {
                uint32_t ad = stA + aLds0 + (uint32_t)(mi * 16 * ASTRIDE_B + s * 32);
                LDS64(a[mi][0], a[mi][2], ad);
                LDS64(a[mi][1], a[mi][3], ad + 8 * ASTRIDE_B);
            }
            uint32_t b[8][2];
#pragma unroll
            for (int nj = 0; nj < 8; nj++) {
                uint32_t bd = stB + bLds0 + (uint32_t)(nj * 8 * ASTRIDE_B + s * 32);
                LDS64(b[nj][0], b[nj][1], bd);
            }
#pragma unroll
            for (int mi = 0; mi < 2; mi++)
#pragma unroll
                for (int nj = 0; nj < 8; nj++)
                    MMA_S8(acc[mi][nj], a[mi], b[nj]);
        }

        if ((c & 1) == 1) {                      // end of n-block: dequant + phases
            const int n0 = (c >> 1) * BN;
#pragma unroll
            for (int mi = 0; mi < 2; mi++)
#pragma unroll
                for (int qh = 0; qh < 2; qh++) {
                    const int r = wm * 32 + mi * 16 + g + 8 * qh;
                    const float sxr = sXs[r];
                    float m = -3.4e38f;
#pragma unroll
                    for (int nj = 0; nj < 8; nj++) {
                        const int n = n0 + wn * 64 + nj * 8 + 2 * t;
                        float s0 = fmaf(__int2float_rn(acc[mi][nj][2 * qh]),
                                        sxr * ses[n], -ehs[n]);
                        float s1 = fmaf(__int2float_rn(acc[mi][nj][2 * qh + 1]),
                                        sxr * ses[n + 1], -ehs[n + 1]);
                        acc[mi][nj][2 * qh]     = __float_as_int(s0);
                        acc[mi][nj][2 * qh + 1] = __float_as_int(s1);
                        m = fmaxf(m, fmaxf(s0, s1));
                    }
                    m = fmaxf(m, __shfl_xor_sync(0xffffffffu, m, 1));
                    m = fmaxf(m, __shfl_xor_sync(0xffffffffu, m, 2));
                    if (t == 0) atomicMax(&sMax[r], fenc(m));
                }
#pragma unroll
            for (int mi = 0; mi < 2; mi++)
#pragma unroll
                for (int qh = 0; qh < 2; qh++) {
                    const int r = wm * 32 + mi * 16 + g + 8 * qh;
                    const float thr = fdec(sMax[r]) - sM[r];
#pragma unroll
                    for (int nj = 0; nj < 8; nj++) {
                        const int n = n0 + wn * 64 + nj * 8 + 2 * t;
#pragma unroll
                        for (int q = 0; q < 2; q++) {
                            float sc = __int_as_float(acc[mi][nj][2 * qh + q]);
                            if (sc >= thr) {
                                int p = atomicAdd(&sCnt[r], 1);
                                if (p < CAP)
                                    sList[r * CAP + p] = make_int2(__float_as_int(sc), n + q);
                            }
                        }
                    }
                }
#pragma unroll
            for (int mi = 0; mi < 2; mi++)
#pragma unroll
                for (int nj = 0; nj < 8; nj++)
#pragma unroll
                    for (int q = 0; q < 4; q++) acc[mi][nj][q] = 0;
        }
        if (c + 2 < NCHUNK) ISSUE_B(c + 2);
    }
    __syncthreads();                              // lists complete

    // ---- fused rescue: one warp per 8 rows ----
    for (int r = wid * 8; r < wid * 8 + 8; r++) {
        const int cnt = sCnt[r];
        int best = 0;
        if (cnt <= CAP) {
            float sc = -3.4e38f; int id = 0;
            if (lane < cnt) { int2 e = sList[r * CAP + lane]; sc = __int_as_float(e.x); id = e.y; }
            float msc = sc;
#pragma unroll
            for (int off = 16; off > 0; off >>= 1)
                msc = fmaxf(msc, __shfl_xor_sync(0xffffffffu, msc, off));
            const float thr = msc - sM[r];
            unsigned surv = __ballot_sync(0xffffffffu, lane < cnt && sc >= thr);
            if (__popc(surv) == 1) {
                best = __shfl_sync(0xffffffffu, id, __ffs(surv) - 1);
            } else {
                const float4* X4 = reinterpret_cast<const float4*>(X + (size_t)(row0 + r) * D);
                float4 x0 = X4[lane], x1 = X4[lane + 32];
                const float xv[8] = { x0.x, x0.y, x0.z, x0.w, x1.x, x1.y, x1.z, x1.w };
                float bh = -3.4e38f, bl = 0.f;
                int besti = NCODES;
                while (surv) {
                    int b = __ffs(surv) - 1; surv &= surv - 1;
                    int idx = __shfl_sync(0xffffffffu, id, b);
                    float h, l;
                    cscore(E, idx, lane, xv, h, l);
                    bool gt = (h > bh) || (h == bh && l > bl);
                    bool eq = (h == bh) && (l == bl);
                    if (gt || (eq && idx < besti)) { bh = h; bl = l; besti = idx; }
                }
                best = besti;
            }
        } else {
            best = full_scan(X, E, row0 + r, lane);   // cold, noinline
        }
        if (lane == 0) sIdx[r] = best;
    }
    __syncthreads();

    // ---- gather: out[row] = E[best] (coalesced float4) ----
    const float4* E4 = reinterpret_cast<const float4*>(E);
    float4*       O4 = reinterpret_cast<float4*>(out);
    const int col = tid & 63;
#pragma unroll
    for (int r = tid >> 6; r < BM; r += 8) {
        int idx = sIdx[r];
        O4[(size_t)(row0 + r) * (D / 4) + col] = E4[(size_t)idx * (D / 4) + col];
    }
#undef ISSUE_B
}

extern "C" void kernel_launch(void* const* d_in, const int* in_sizes, int n_in,
                              void* d_out, int out_size) {
    const float* x = (const float*)d_in[0];     // [16,1024,256] f32
    const float* E = (const float*)d_in[1];     // [1024,256]    f32
    float* out = (float*)d_out;

    prep_e<<<NCODES / 8, 256>>>(E);

    cudaFuncSetAttribute(vq_mma, cudaFuncAttributeMaxDynamicSharedMemorySize, SMEM_TOTAL);
    vq_mma<<<ROWS_TOTAL / BM, NT, SMEM_TOTAL>>>(x, E, out);
}